// round 1
// baseline (speedup 1.0000x reference)
#include <cuda_runtime.h>
#include <cstdint>

#define INPUT_DIM 1024
#define DAY_EMB   8
#define PRED_LEN  96
#define HIDDEN    512
#define BATCH     4096
#define W1_ROWS   (INPUT_DIM + DAY_EMB)   // 1032

#define BM 128
#define BN 128
#define BK 16
#define NT (HIDDEN / BN)                  // 4 n-tiles
#define MT (BATCH / BM)                   // 32 m-tiles

// Scratch (allocation-free rule: __device__ globals)
__device__ float g_bias[PRED_LEN * HIDDEN];              // c[p][h] = day_emb@W1e + b1
__device__ float g_part[NT * BATCH * PRED_LEN];          // partial sums per n-tile

__device__ __forceinline__ float to_tf32(float x) {
    float r;
    asm("cvt.rna.tf32.f32 %0, %1;" : "=f"(r) : "f"(x));
    return r;
}

// ---------------------------------------------------------------------------
// Kernel 1: bias precompute  c[p][h] = b1[p][h] + sum_e day_emb[p][e]*W1[p][1024+e][h]
// ---------------------------------------------------------------------------
__global__ void bias_kernel(const float* __restrict__ day_emb,
                            const float* __restrict__ W1,
                            const float* __restrict__ b1) {
    int p = blockIdx.x;
    int h = threadIdx.x;
    const float* w = W1 + (size_t)p * W1_ROWS * HIDDEN + (size_t)INPUT_DIM * HIDDEN;
    float s = b1[p * HIDDEN + h];
    #pragma unroll
    for (int e = 0; e < DAY_EMB; ++e)
        s += day_emb[p * DAY_EMB + e] * w[e * HIDDEN + h];
    g_bias[p * HIDDEN + h] = s;
}

// ---------------------------------------------------------------------------
// Kernel 2: fused tf32 GEMM (x @ W1x[p]) + bias + ReLU + dot(W2[p]) -> partials
//   grid: (NT, MT, PRED_LEN), block: 256 threads (8 warps, 4x2 warp grid)
//   warp tile: 32(m) x 64(n); mma m16n8k8 tf32
// ---------------------------------------------------------------------------
__global__ void __launch_bounds__(256, 2)
mlp_gemm_kernel(const float* __restrict__ x,
                const float* __restrict__ W1,
                const float* __restrict__ W2) {
    const int nt = blockIdx.x;
    const int mt = blockIdx.y;
    const int p  = blockIdx.z;

    const int tid  = threadIdx.x;
    const int lane = tid & 31;
    const int warp = tid >> 5;
    const int wm   = warp >> 1;   // 0..3
    const int wn   = warp & 1;    // 0..1

    __shared__ float As[BK][BM + 4];   // A stored transposed: As[k][m]
    __shared__ float Bs[BK][BN + 4];   // Bs[k][n]
    __shared__ float cs[BN];           // bias slice
    __shared__ float ws[BN];           // W2 slice
    __shared__ float outred[2][BM];    // per-wn row sums

    const int m0 = mt * BM;
    const int n0 = nt * BN;

    if (tid < BN) {
        cs[tid] = g_bias[p * HIDDEN + n0 + tid];
        ws[tid] = W2[p * HIDDEN + n0 + tid];
    }

    const float* Aptr = x + (size_t)m0 * INPUT_DIM;
    const float* Bptr = W1 + (size_t)p * W1_ROWS * HIDDEN + n0;

    // accumulators: acc[mi][ni][4]
    float acc[2][8][4];
    #pragma unroll
    for (int mi = 0; mi < 2; ++mi)
        #pragma unroll
        for (int ni = 0; ni < 8; ++ni)
            #pragma unroll
            for (int q = 0; q < 4; ++q)
                acc[mi][ni][q] = 0.0f;

    // global->reg staging
    float4 aReg[2], bReg[2];
    const int ar = tid >> 2;        // 0..63 (two iters: +0,+64)
    const int aj = tid & 3;         // float4 within the 16-wide k-slice
    const int bk = tid >> 5;        // 0..7  (two iters: +0,+8)
    const int bs = tid & 31;        // float4 within 128-wide n-slice

    auto load_tile = [&](int k0) {
        #pragma unroll
        for (int it = 0; it < 2; ++it) {
            aReg[it] = *reinterpret_cast<const float4*>(
                Aptr + (size_t)(ar + it * 64) * INPUT_DIM + k0 + aj * 4);
            bReg[it] = *reinterpret_cast<const float4*>(
                Bptr + (size_t)(k0 + bk + it * 8) * HIDDEN + bs * 4);
        }
    };

    load_tile(0);

    const int r = lane >> 2;     // groupID
    const int c = lane & 3;      // thread-in-group

    for (int kt = 0; kt < INPUT_DIM / BK; ++kt) {
        __syncthreads();
        // store staged tile to smem (converted to tf32)
        #pragma unroll
        for (int it = 0; it < 2; ++it) {
            int row = ar + it * 64;
            As[aj * 4 + 0][row] = to_tf32(aReg[it].x);
            As[aj * 4 + 1][row] = to_tf32(aReg[it].y);
            As[aj * 4 + 2][row] = to_tf32(aReg[it].z);
            As[aj * 4 + 3][row] = to_tf32(aReg[it].w);
            int krow = bk + it * 8;
            Bs[krow][bs * 4 + 0] = to_tf32(bReg[it].x);
            Bs[krow][bs * 4 + 1] = to_tf32(bReg[it].y);
            Bs[krow][bs * 4 + 2] = to_tf32(bReg[it].z);
            Bs[krow][bs * 4 + 3] = to_tf32(bReg[it].w);
        }
        __syncthreads();

        if (kt + 1 < INPUT_DIM / BK) load_tile((kt + 1) * BK);

        #pragma unroll
        for (int kb = 0; kb < BK; kb += 8) {
            uint32_t a[2][4], b[8][2];
            #pragma unroll
            for (int mi = 0; mi < 2; ++mi) {
                int mrow = wm * 32 + mi * 16 + r;
                a[mi][0] = __float_as_uint(As[kb + c    ][mrow]);
                a[mi][1] = __float_as_uint(As[kb + c    ][mrow + 8]);
                a[mi][2] = __float_as_uint(As[kb + c + 4][mrow]);
                a[mi][3] = __float_as_uint(As[kb + c + 4][mrow + 8]);
            }
            #pragma unroll
            for (int ni = 0; ni < 8; ++ni) {
                int ncol = wn * 64 + ni * 8 + r;
                b[ni][0] = __float_as_uint(Bs[kb + c    ][ncol]);
                b[ni][1] = __float_as_uint(Bs[kb + c + 4][ncol]);
            }
            #pragma unroll
            for (int mi = 0; mi < 2; ++mi)
                #pragma unroll
                for (int ni = 0; ni < 8; ++ni) {
                    asm volatile(
                        "mma.sync.aligned.m16n8k8.row.col.f32.tf32.tf32.f32 "
                        "{%0,%1,%2,%3}, {%4,%5,%6,%7}, {%8,%9}, {%0,%1,%2,%3};"
                        : "+f"(acc[mi][ni][0]), "+f"(acc[mi][ni][1]),
                          "+f"(acc[mi][ni][2]), "+f"(acc[mi][ni][3])
                        : "r"(a[mi][0]), "r"(a[mi][1]), "r"(a[mi][2]), "r"(a[mi][3]),
                          "r"(b[ni][0]), "r"(b[ni][1]));
                }
        }
    }

    // epilogue: bias + relu + multiply by W2, reduce over n
    __syncthreads();
    #pragma unroll
    for (int mi = 0; mi < 2; ++mi) {
        float rs0 = 0.0f, rs1 = 0.0f;   // rows (r) and (r+8) of this 16-row tile
        #pragma unroll
        for (int ni = 0; ni < 8; ++ni) {
            int col = wn * 64 + ni * 8 + c * 2;
            float h0 = acc[mi][ni][0] + cs[col];
            float h1 = acc[mi][ni][1] + cs[col + 1];
            float h2 = acc[mi][ni][2] + cs[col];
            float h3 = acc[mi][ni][3] + cs[col + 1];
            rs0 += fmaxf(h0, 0.0f) * ws[col] + fmaxf(h1, 0.0f) * ws[col + 1];
            rs1 += fmaxf(h2, 0.0f) * ws[col] + fmaxf(h3, 0.0f) * ws[col + 1];
        }
        // reduce over the 4 lanes of the quad (different n columns)
        #pragma unroll
        for (int off = 1; off < 4; off <<= 1) {
            rs0 += __shfl_xor_sync(0xffffffffu, rs0, off);
            rs1 += __shfl_xor_sync(0xffffffffu, rs1, off);
        }
        if ((lane & 3) == 0) {
            int row = wm * 32 + mi * 16 + r;
            outred[wn][row]     = rs0;
            outred[wn][row + 8] = rs1;
        }
    }
    __syncthreads();

    if (tid < BM) {
        float s = outred[0][tid] + outred[1][tid];
        g_part[((size_t)nt * BATCH + (m0 + tid)) * PRED_LEN + p] = s;
    }
}

// ---------------------------------------------------------------------------
// Kernel 3: reduce partials + b2  ->  out[b][p]   (deterministic, no atomics)
// ---------------------------------------------------------------------------
__global__ void reduce_kernel(const float* __restrict__ b2, float* __restrict__ out) {
    int idx = blockIdx.x * blockDim.x + threadIdx.x;
    if (idx >= BATCH * PRED_LEN) return;
    int p = idx % PRED_LEN;
    float s = b2[p];
    #pragma unroll
    for (int nt = 0; nt < NT; ++nt)
        s += g_part[(size_t)nt * BATCH * PRED_LEN + idx];
    out[idx] = s;
}

// ---------------------------------------------------------------------------
extern "C" void kernel_launch(void* const* d_in, const int* in_sizes, int n_in,
                              void* d_out, int out_size) {
    const float* x       = (const float*)d_in[0];
    const float* day_emb = (const float*)d_in[1];
    const float* W1      = (const float*)d_in[2];
    const float* b1      = (const float*)d_in[3];
    const float* W2      = (const float*)d_in[4];
    const float* b2      = (const float*)d_in[5];
    float* out = (float*)d_out;

    bias_kernel<<<PRED_LEN, HIDDEN>>>(day_emb, W1, b1);

    dim3 grid(NT, MT, PRED_LEN);
    mlp_gemm_kernel<<<grid, 256>>>(x, W1, W2);

    int total = BATCH * PRED_LEN;
    reduce_kernel<<<(total + 255) / 256, 256>>>(b2, out);
}